// round 14
// baseline (speedup 1.0000x reference)
#include <cuda_runtime.h>
#include <cuda_bf16.h>
#include <math.h>
#include <stdint.h>

// Problem constants
#define LSEQ 2048
#define DMODEL 4096
#define NH 32
#define NKV 8
#define HDIM 128
#define QKVN 6144            // 32*128 + 2*8*128
#define KOFF 4096
#define VOFF 5120
#define ATT_SCALE 0.08838834764831843f
#define LOG2E 1.44269504089f

// Scratch (no cudaMalloc allowed)
__device__ float g_qkv[(size_t)LSEQ * QKVN];       // 50 MB
__device__ float g_o[(size_t)LSEQ * DMODEL];       // 33 MB
__device__ float g_wqkvT[(size_t)QKVN * DMODEL];   // 100 MB
__device__ float g_woT[(size_t)DMODEL * DMODEL];   // 67 MB
// Packed bf16 hi/lo K and V^T (computed once post-RoPE, shared by all attn CTAs)
__device__ uint32_t g_kp[(size_t)NKV * LSEQ * 128];      // [kvh][l][hi 0..63 | lo 64..127]
__device__ uint32_t g_vtp[(size_t)NKV * HDIM * 2048];    // [kvh][d][hi kp 0..1023 | lo 1024..2047]

// ---------------------------------------------------------------------------
// Helpers
// ---------------------------------------------------------------------------
__device__ __forceinline__ uint32_t smem_u32(const void* p) {
    uint32_t a;
    asm("{ .reg .u64 t; cvta.to.shared.u64 t, %1; cvt.u32.u64 %0, t; }" : "=r"(a) : "l"(p));
    return a;
}
__device__ __forceinline__ float f32_to_tf32(float v) {
    uint32_t o;
    asm("cvt.rna.tf32.f32 %0, %1;" : "=r"(o) : "f"(v));
    return __uint_as_float(o);
}
__device__ __forceinline__ uint32_t rna_u32(uint32_t x) {
    uint32_t o;
    asm("cvt.rna.tf32.f32 %0, %1;" : "=r"(o) : "f"(__uint_as_float(x)));
    return o;
}
#define CP_ASYNC16(dst, src) \
    asm volatile("cp.async.cg.shared.global [%0], [%1], 16;" :: "r"(dst), "l"(src))
#define CP_COMMIT() asm volatile("cp.async.commit_group;")
#define CP_WAIT(n)  asm volatile("cp.async.wait_group %0;" :: "n"(n))

#define LDSM_X4(r0, r1, r2, r3, addr) \
    asm volatile("ldmatrix.sync.aligned.m8n8.x4.shared.b16 {%0,%1,%2,%3}, [%4];" \
                 : "=r"(r0), "=r"(r1), "=r"(r2), "=r"(r3) : "r"(addr))

__device__ __forceinline__ void mma_tf32(float* d, const uint32_t* a, const uint32_t* b) {
    asm volatile(
        "mma.sync.aligned.m16n8k8.row.col.f32.tf32.tf32.f32 "
        "{%0,%1,%2,%3}, {%4,%5,%6,%7}, {%8,%9}, {%0,%1,%2,%3};"
        : "+f"(d[0]), "+f"(d[1]), "+f"(d[2]), "+f"(d[3])
        : "r"(a[0]), "r"(a[1]), "r"(a[2]), "r"(a[3]), "r"(b[0]), "r"(b[1]));
}
__device__ __forceinline__ void mma_bf16(float* d, const uint32_t* a, const uint32_t* b) {
    asm volatile(
        "mma.sync.aligned.m16n8k16.row.col.f32.bf16.bf16.f32 "
        "{%0,%1,%2,%3}, {%4,%5,%6,%7}, {%8,%9}, {%0,%1,%2,%3};"
        : "+f"(d[0]), "+f"(d[1]), "+f"(d[2]), "+f"(d[3])
        : "r"(a[0]), "r"(a[1]), "r"(a[2]), "r"(a[3]), "r"(b[0]), "r"(b[1]));
}

// Pack (v0, v1) into bf16x2 hi word and residual-lo word. v0 -> low half.
__device__ __forceinline__ void pack_hilo(float v0, float v1, uint32_t& hi, uint32_t& lo) {
    __nv_bfloat162 h2 = __floats2bfloat162_rn(v0, v1);
    uint32_t hw = *(uint32_t*)&h2;
    float h0 = __uint_as_float(hw << 16);
    float h1 = __uint_as_float(hw & 0xffff0000u);
    __nv_bfloat162 l2 = __floats2bfloat162_rn(v0 - h0, v1 - h1);
    hi = hw;
    lo = *(uint32_t*)&l2;
}

// ---------------------------------------------------------------------------
// Persistent tf32 GEMM: C[M,N] = A[M,K] @ BT[N,K]^T.
// A raw fp32 (rna in-register post-ldmatrix); BT pre-rounded K-major.
// Grid = 296 persistent CTAs (2/SM); outer tile loop NOT unrolled
// (#pragma unroll 1 — the R10 compile blowup suspect).
// ---------------------------------------------------------------------------
#define BM 128
#define BN 128
#define BK 32
#define NSTG 3
#define PADW 36
#define ASTG (BM * PADW)
#define STGF (2 * BM * PADW)
#define GEMM_SMEM (NSTG * STGF * 4)
#define GEMM_GRID 296

__global__ __launch_bounds__(256, 2) void gemm_mma(
    const float* __restrict__ A, const float* __restrict__ BT,
    float* __restrict__ C, int M, int N, int K)
{
    extern __shared__ float sm[];
    const int tid = threadIdx.x;
    const int wid = tid >> 5, lane = tid & 31;
    const int wm = wid & 3, wn = wid >> 2;
    const int g = lane >> 2, c = lane & 3;
    const int NC = K / BK;
    const int ntn = N / BN;
    const int ntiles = (M / BM) * ntn;

    const int mat = lane >> 3, r8 = lane & 7;
    const int a_row_l = wm * 32 + (mat & 1) * 8 + r8;
    const int a_k_l   = (mat >> 1) * 4;
    const int b_row_l = wn * 64 + (mat >> 1) * 8 + r8;
    const int b_k_l   = (mat & 1) * 4;

    #pragma unroll 1
    for (int t = blockIdx.x; t < ntiles; t += GEMM_GRID) {
        const int bm = (t / ntn) * BM;
        const int bn = (t % ntn) * BN;

        float acc[2][8][4];
        #pragma unroll
        for (int mf = 0; mf < 2; mf++)
            #pragma unroll
            for (int nf = 0; nf < 8; nf++)
                #pragma unroll
                for (int i = 0; i < 4; i++) acc[mf][nf][i] = 0.f;

        auto load_stage = [&](int ct, int s) {
            float* base = sm + s * STGF;
            const int kt = ct * BK;
            #pragma unroll
            for (int h = 0; h < 4; h++) {
                int idx = tid + h * 256;
                int row = idx >> 3, c8 = idx & 7;
                CP_ASYNC16(smem_u32(base + row * PADW + c8 * 4),
                           A + (size_t)(bm + row) * K + kt + c8 * 4);
            }
            #pragma unroll
            for (int h = 0; h < 4; h++) {
                int idx = tid + h * 256;
                int row = idx >> 3, c8 = idx & 7;
                CP_ASYNC16(smem_u32(base + ASTG + row * PADW + c8 * 4),
                           BT + (size_t)(bn + row) * K + kt + c8 * 4);
            }
            CP_COMMIT();
        };

        __syncthreads();   // protect stage buffers from previous tile's readers
        load_stage(0, 0);
        load_stage(1, 1);

        #pragma unroll 1
        for (int ct = 0; ct < NC; ct++) {
            CP_WAIT(1);
            __syncthreads();
            if (ct + 2 < NC) load_stage(ct + 2, (ct + 2) % NSTG);
            else CP_COMMIT();

            const float* As = sm + (ct % NSTG) * STGF;
            const float* Bs = As + ASTG;
            const uint32_t a_base = smem_u32(As + a_row_l * PADW + a_k_l);
            const uint32_t b_base = smem_u32(Bs + b_row_l * PADW + b_k_l);

            #pragma unroll
            for (int kk = 0; kk < 4; kk++) {
                uint32_t af[2][4], bf[8][2];
                #pragma unroll
                for (int mf = 0; mf < 2; mf++) {
                    LDSM_X4(af[mf][0], af[mf][1], af[mf][2], af[mf][3],
                            a_base + (mf * 16 * PADW + kk * 8) * 4);
                    #pragma unroll
                    for (int i = 0; i < 4; i++) af[mf][i] = rna_u32(af[mf][i]);
                }
                #pragma unroll
                for (int np = 0; np < 4; np++)
                    LDSM_X4(bf[2 * np][0], bf[2 * np][1], bf[2 * np + 1][0], bf[2 * np + 1][1],
                            b_base + (np * 16 * PADW + kk * 8) * 4);
                #pragma unroll
                for (int mf = 0; mf < 2; mf++)
                    #pragma unroll
                    for (int nf = 0; nf < 8; nf++)
                        mma_tf32(acc[mf][nf], af[mf], bf[nf]);
            }
        }

        #pragma unroll
        for (int mf = 0; mf < 2; mf++) {
            #pragma unroll
            for (int nf = 0; nf < 8; nf++) {
                int row = bm + wm * 32 + mf * 16 + g;
                int col = bn + wn * 64 + nf * 8 + 2 * c;
                *(float2*)&C[(size_t)row * N + col] = make_float2(acc[mf][nf][0], acc[mf][nf][1]);
                *(float2*)&C[(size_t)(row + 8) * N + col] = make_float2(acc[mf][nf][2], acc[mf][nf][3]);
            }
        }
    }
}

// ---------------------------------------------------------------------------
// Transpose + tf32 round: dst[C][R] = rna(src[R][C])
// ---------------------------------------------------------------------------
__global__ void transpose_rna(const float* __restrict__ src, float* __restrict__ dst,
                              int R, int C)
{
    __shared__ float t[32][33];
    const int bx = blockIdx.x * 32, by = blockIdx.y * 32;
    const int x = threadIdx.x, y0 = threadIdx.y;
    #pragma unroll
    for (int i = 0; i < 4; i++) {
        int r = by + y0 + i * 8;
        t[y0 + i * 8][x] = f32_to_tf32(src[(size_t)r * C + bx + x]);
    }
    __syncthreads();
    #pragma unroll
    for (int i = 0; i < 4; i++) {
        int c = bx + y0 + i * 8;
        dst[(size_t)c * R + by + x] = t[x][y0 + i * 8];
    }
}

// ---------------------------------------------------------------------------
// RoPE (standalone — R13 fusion cost more than it saved via reg spills)
// ---------------------------------------------------------------------------
__global__ void rope_kernel(const float* __restrict__ cosp,
                            const float* __restrict__ sinp)
{
    const int l = blockIdx.x;
    const int y = blockIdx.y;
    const int t = threadIdx.x;
    const int off = (y < NH) ? y * HDIM : KOFF + (y - NH) * HDIM;
    const size_t base = (size_t)l * QKVN + off;

    float v  = g_qkv[base + t];
    int pj   = (t < 32) ? t + 32 : t - 32;
    float pv = g_qkv[base + pj];
    float cc = cosp[l * 64 + t];
    float ss = sinp[l * 64 + t];
    float o = (t < 32) ? fmaf(v, cc, -pv * ss) : fmaf(v, cc, pv * ss);
    __syncthreads();
    g_qkv[base + t] = o;
}

// ---------------------------------------------------------------------------
// Pack K (post-RoPE): g_kp[kvh][l][hi j | lo 64+j]
// ---------------------------------------------------------------------------
__global__ void pack_k_kernel()
{
    const int l = blockIdx.x, kvh = blockIdx.y, j = threadIdx.x;
    const float* src = &g_qkv[(size_t)l * QKVN + KOFF + kvh * HDIM];
    uint32_t hi, lo;
    pack_hilo(src[2 * j], src[2 * j + 1], hi, lo);
    uint32_t* dst = &g_kp[((size_t)kvh * LSEQ + l) * 128];
    dst[j] = hi;
    dst[64 + j] = lo;
}

// ---------------------------------------------------------------------------
// Pack V transposed: g_vtp[kvh][d][hi kp | lo 1024+kp]
// ---------------------------------------------------------------------------
__global__ void pack_vt_kernel()
{
    __shared__ float sf[128][66];
    const int l0 = blockIdx.x * 64, kvh = blockIdx.y;
    const int tid = threadIdx.x;

    #pragma unroll
    for (int i = 0; i < 32; i++) {
        int idx = tid + i * 256;
        int ll = idx >> 7, d = idx & 127;
        sf[d][ll] = g_qkv[(size_t)(l0 + ll) * QKVN + VOFF + kvh * HDIM + d];
    }
    __syncthreads();

    const int kp_l = tid & 31;
    #pragma unroll
    for (int i = 0; i < 16; i++) {
        int d = (tid >> 5) + i * 8;
        uint32_t hi, lo;
        pack_hilo(sf[d][2 * kp_l], sf[d][2 * kp_l + 1], hi, lo);
        size_t base = ((size_t)kvh * HDIM + d) * 2048 + (l0 >> 1) + kp_l;
        g_vtp[base] = hi;
        g_vtp[base + 1024] = lo;
    }
}

// ---------------------------------------------------------------------------
// Flash attention (R8 winner): bf16 hi/lo split mma; 256 threads,
// 8 warps x 16 q-rows; K/V via cp.async pre-packed.
// ---------------------------------------------------------------------------
#define QW 68
#define VW 44
#define QHI_OFF 0
#define QLO_OFF (128 * QW)
#define KBUF_OFF 17408
#define VTH_OFF (KBUF_OFF + 2 * 8704)
#define VTL_OFF (VTH_OFF + 128 * VW)
#define ATT_SMEM_WORDS (VTL_OFF + 128 * VW)
#define ATT_SMEM_BYTES (ATT_SMEM_WORDS * 4)

__global__ __launch_bounds__(256, 1) void attn_kernel()
{
    extern __shared__ uint32_t sw[];

    const int qt = (int)gridDim.x - 1 - (int)blockIdx.x;
    const int h  = blockIdx.y;
    const int kvh = h >> 2;
    const int qoff = h * HDIM;
    const int qbase = qt * 128;

    const int tid = threadIdx.x;
    const int w = tid >> 5, lane = tid & 31;
    const int g = lane >> 2, cc = lane & 3;

    #pragma unroll
    for (int i = 0; i < 16; i++) {
        int idx = tid + i * 256;
        int row = idx >> 5, c4 = idx & 31;
        float4 v = *(const float4*)&g_qkv[(size_t)(qbase + row) * QKVN + qoff + c4 * 4];
        uint32_t h0, l0, h1, l1;
        pack_hilo(v.x, v.y, h0, l0);
        pack_hilo(v.z, v.w, h1, l1);
        int wo = row * QW + c4 * 2;
        sw[QHI_OFF + wo] = h0; sw[QHI_OFF + wo + 1] = h1;
        sw[QLO_OFF + wo] = l0; sw[QLO_OFF + wo + 1] = l1;
    }

    auto load_k = [&](int kb, int buf) {
        const uint32_t* src0 = &g_kp[((size_t)kvh * LSEQ + kb) * 128];
        const int base = KBUF_OFF + buf * 8704;
        #pragma unroll
        for (int i = 0; i < 8; i++) {
            int idx = tid + i * 256;
            int half = idx >> 10;
            int r = (idx >> 4) & 63;
            int ch = idx & 15;
            int woff = base + half * 4352 + r * QW + ch * 4;
            CP_ASYNC16(smem_u32(sw + woff), src0 + (size_t)r * 128 + half * 64 + ch * 4);
        }
        CP_COMMIT();
    };
    auto load_v = [&](int kb) {
        const uint32_t* src0 = &g_vtp[(size_t)kvh * HDIM * 2048 + (kb >> 1)];
        #pragma unroll
        for (int i = 0; i < 8; i++) {
            int idx = tid + i * 256;
            int half = idx >> 10;
            int d = (idx >> 3) & 127;
            int ch = idx & 7;
            int woff = (half ? VTL_OFF : VTH_OFF) + d * VW + ch * 4;
            CP_ASYNC16(smem_u32(sw + woff), src0 + (size_t)d * 2048 + half * 1024 + ch * 4);
        }
        CP_COMMIT();
    };

    float m0 = -1e30f, m1 = -1e30f, l0s = 0.f, l1s = 0.f;
    float o[16][4];
    #pragma unroll
    for (int j = 0; j < 16; j++)
        #pragma unroll
        for (int i = 0; i < 4; i++) o[j][i] = 0.f;

    const int r0 = qbase + w * 16 + g;
    const int r1 = r0 + 8;
    const float sl2e = ATT_SCALE * LOG2E;
    const int nkt = 2 * qt + 2;

    load_k(0, 0);

    for (int kt = 0; kt < nkt; kt++) {
        const int kb = kt * 64;
        const int kbase = KBUF_OFF + (kt & 1) * 8704;

        __syncthreads();
        load_v(kb);
        const bool more = (kt + 1 < nkt);
        if (more) load_k(kb + 64, (kt + 1) & 1);

        if (more) CP_WAIT(2); else CP_WAIT(1);
        __syncthreads();

        float s[8][4];
        #pragma unroll
        for (int j = 0; j < 8; j++)
            #pragma unroll
            for (int i = 0; i < 4; i++) s[j][i] = 0.f;

        #pragma unroll
        for (int kk = 0; kk < 8; kk++) {
            uint32_t ah[4], al[4];
            int ab = (w * 16 + g) * QW + kk * 8 + cc;
            ah[0] = sw[QHI_OFF + ab];              al[0] = sw[QLO_OFF + ab];
            ah[1] = sw[QHI_OFF + ab + 8 * QW];     al[1] = sw[QLO_OFF + ab + 8 * QW];
            ah[2] = sw[QHI_OFF + ab + 4];          al[2] = sw[QLO_OFF + ab + 4];
            ah[3] = sw[QHI_OFF + ab + 8 * QW + 4]; al[3] = sw[QLO_OFF + ab + 8 * QW + 4];
            #pragma unroll
            for (int j = 0; j < 8; j++) {
                uint32_t bh[2], bl[2];
                int bb = kbase + (j * 8 + g) * QW + kk * 8 + cc;
                bh[0] = sw[bb];        bh[1] = sw[bb + 4];
                bl[0] = sw[bb + 4352]; bl[1] = sw[bb + 4352 + 4];
                mma_bf16(s[j], ah, bh);
                mma_bf16(s[j], al, bh);
                mma_bf16(s[j], ah, bl);
            }
        }

        if (kt >= 2 * qt) {
            #pragma unroll
            for (int j = 0; j < 8; j++) {
                int colb = kb + j * 8 + 2 * cc;
                if (colb > r0)     s[j][0] = -1e30f;
                if (colb + 1 > r0) s[j][1] = -1e30f;
                if (colb > r1)     s[j][2] = -1e30f;
                if (colb + 1 > r1) s[j][3] = -1e30f;
            }
        }

        float mx0 = -1e30f, mx1 = -1e30f;
        #pragma unroll
        for (int j = 0; j < 8; j++) {
            mx0 = fmaxf(mx0, fmaxf(s[j][0], s[j][1]));
            mx1 = fmaxf(mx1, fmaxf(s[j][2], s[j][3]));
        }
        mx0 = fmaxf(mx0, __shfl_xor_sync(0xffffffffu, mx0, 1));
        mx0 = fmaxf(mx0, __shfl_xor_sync(0xffffffffu, mx0, 2));
        mx1 = fmaxf(mx1, __shfl_xor_sync(0xffffffffu, mx1, 1));
        mx1 = fmaxf(mx1, __shfl_xor_sync(0xffffffffu, mx1, 2));

        float mn0 = fmaxf(m0, mx0), mn1 = fmaxf(m1, mx1);
        float corr0 = exp2f((m0 - mn0) * sl2e);
        float corr1 = exp2f((m1 - mn1) * sl2e);
        m0 = mn0; m1 = mn1;

        uint32_t Ph0[8], Pl0[8], Ph1[8], Pl1[8];
        float sum0 = 0.f, sum1 = 0.f;
        #pragma unroll
        for (int j = 0; j < 8; j++) {
            float p0 = exp2f((s[j][0] - m0) * sl2e);
            float p1 = exp2f((s[j][1] - m0) * sl2e);
            float p2 = exp2f((s[j][2] - m1) * sl2e);
            float p3 = exp2f((s[j][3] - m1) * sl2e);
            sum0 += p0 + p1; sum1 += p2 + p3;
            pack_hilo(p0, p1, Ph0[j], Pl0[j]);
            pack_hilo(p2, p3, Ph1[j], Pl1[j]);
        }
        sum0 += __shfl_xor_sync(0xffffffffu, sum0, 1);
        sum0 += __shfl_xor_sync(0xffffffffu, sum0, 2);
        sum1 += __shfl_xor_sync(0xffffffffu, sum1, 1);
        sum1 += __shfl_xor_sync(0xffffffffu, sum1, 2);
        l0s = l0s * corr0 + sum0;
        l1s = l1s * corr1 + sum1;

        #pragma unroll
        for (int j = 0; j < 16; j++) {
            o[j][0] *= corr0; o[j][1] *= corr0;
            o[j][2] *= corr1; o[j][3] *= corr1;
        }

        if (more) CP_WAIT(1); else CP_WAIT(0);
        __syncthreads();

        #pragma unroll
        for (int kk = 0; kk < 4; kk++) {
            uint32_t ah[4] = {Ph0[2 * kk], Ph1[2 * kk], Ph0[2 * kk + 1], Ph1[2 * kk + 1]};
            uint32_t al[4] = {Pl0[2 * kk], Pl1[2 * kk], Pl0[2 * kk + 1], Pl1[2 * kk + 1]};
            #pragma unroll
            for (int jn = 0; jn < 16; jn++) {
                uint32_t bh[2], bl[2];
                int vb = (jn * 8 + g) * VW + kk * 8 + cc;
                bh[0] = sw[VTH_OFF + vb]; bh[1] = sw[VTH_OFF + vb + 4];
                bl[0] = sw[VTL_OFF + vb]; bl[1] = sw[VTL_OFF + vb + 4];
                mma_bf16(o[jn], ah, bh);
                mma_bf16(o[jn], al, bh);
                mma_bf16(o[jn], ah, bl);
            }
        }
    }

    // epilogue: normalize and write (O-proj rna's its A-fragments in-register)
    float li0 = 1.0f / l0s, li1 = 1.0f / l1s;
    #pragma unroll
    for (int jn = 0; jn < 16; jn++) {
        int col = h * HDIM + jn * 8 + 2 * cc;
        *(float2*)&g_o[(size_t)r0 * DMODEL + col] =
            make_float2(o[jn][0] * li0, o[jn][1] * li0);
        *(float2*)&g_o[(size_t)r1 * DMODEL + col] =
            make_float2(o[jn][2] * li1, o[jn][3] * li1);
    }
}

// ---------------------------------------------------------------------------
// Launch
// ---------------------------------------------------------------------------
extern "C" void kernel_launch(void* const* d_in, const int* in_sizes, int n_in,
                              void* d_out, int out_size)
{
    const float* x     = (const float*)d_in[0];
    const float* cosp  = (const float*)d_in[2];
    const float* sinp  = (const float*)d_in[3];
    const float* w_qkv = (const float*)d_in[4];
    const float* w_o   = (const float*)d_in[5];
    float* out = (float*)d_out;

    float *qkv_p, *o_p, *wqkvT_p, *woT_p;
    cudaGetSymbolAddress((void**)&qkv_p, g_qkv);
    cudaGetSymbolAddress((void**)&o_p, g_o);
    cudaGetSymbolAddress((void**)&wqkvT_p, g_wqkvT);
    cudaGetSymbolAddress((void**)&woT_p, g_woT);

    cudaFuncSetAttribute(gemm_mma, cudaFuncAttributeMaxDynamicSharedMemorySize, GEMM_SMEM);
    cudaFuncSetAttribute(attn_kernel, cudaFuncAttributeMaxDynamicSharedMemorySize, ATT_SMEM_BYTES);

    // 0. transpose weights to K-major + tf32 round
    transpose_rna<<<dim3(QKVN / 32, DMODEL / 32), dim3(32, 8)>>>(w_qkv, wqkvT_p, DMODEL, QKVN);
    transpose_rna<<<dim3(DMODEL / 32, DMODEL / 32), dim3(32, 8)>>>(w_o, woT_p, DMODEL, DMODEL);

    // 1. QKV projection (persistent tf32 mma)
    gemm_mma<<<GEMM_GRID, 256, GEMM_SMEM>>>(x, wqkvT_p, qkv_p, LSEQ, QKVN, DMODEL);

    // 2. RoPE
    rope_kernel<<<dim3(LSEQ, NH + NKV), 64>>>(cosp, sinp);

    // 3. Pack K / V^T to bf16 hi/lo once
    pack_k_kernel<<<dim3(LSEQ, NKV), 64>>>();
    pack_vt_kernel<<<dim3(LSEQ / 64, NKV), 256>>>();

    // 4. Flash attention (R8 config)
    attn_kernel<<<dim3(LSEQ / 128, NH), 256, ATT_SMEM_BYTES>>>();

    // 5. Output projection (persistent tf32 mma)
    gemm_mma<<<GEMM_GRID, 256, GEMM_SMEM>>>(o_p, woT_p, out, LSEQ, DMODEL, DMODEL);
}

// round 15
// speedup vs baseline: 1.0757x; 1.0757x over previous
#include <cuda_runtime.h>
#include <cuda_bf16.h>
#include <math.h>
#include <stdint.h>

// Problem constants
#define LSEQ 2048
#define DMODEL 4096
#define NH 32
#define NKV 8
#define HDIM 128
#define QKVN 6144            // 32*128 + 2*8*128
#define KOFF 4096
#define VOFF 5120
#define ATT_SCALE 0.08838834764831843f
#define LOG2E 1.44269504089f

// Scratch (no cudaMalloc allowed)
__device__ float g_qkv[(size_t)LSEQ * QKVN];       // 50 MB
__device__ float g_o[(size_t)LSEQ * DMODEL];       // 33 MB
__device__ float g_xr[(size_t)LSEQ * DMODEL];      // 33 MB (tf32-rounded x)
__device__ float g_wqkvT[(size_t)QKVN * DMODEL];   // 100 MB
__device__ float g_woT[(size_t)DMODEL * DMODEL];   // 67 MB
// Packed bf16 hi/lo K and V^T (computed once post-RoPE, shared by all attn CTAs)
__device__ uint32_t g_kp[(size_t)NKV * LSEQ * 128];      // [kvh][l][hi 0..63 | lo 64..127]
__device__ uint32_t g_vtp[(size_t)NKV * HDIM * 2048];    // [kvh][d][hi kp 0..1023 | lo 1024..2047]

// ---------------------------------------------------------------------------
// Helpers
// ---------------------------------------------------------------------------
__device__ __forceinline__ uint32_t smem_u32(const void* p) {
    uint32_t a;
    asm("{ .reg .u64 t; cvta.to.shared.u64 t, %1; cvt.u32.u64 %0, t; }" : "=r"(a) : "l"(p));
    return a;
}
__device__ __forceinline__ float f32_to_tf32(float v) {
    uint32_t o;
    asm("cvt.rna.tf32.f32 %0, %1;" : "=r"(o) : "f"(v));
    return __uint_as_float(o);
}
#define CP_ASYNC16(dst, src) \
    asm volatile("cp.async.cg.shared.global [%0], [%1], 16;" :: "r"(dst), "l"(src))
#define CP_COMMIT() asm volatile("cp.async.commit_group;")
#define CP_WAIT(n)  asm volatile("cp.async.wait_group %0;" :: "n"(n))

#define LDSM_X4(r0, r1, r2, r3, addr) \
    asm volatile("ldmatrix.sync.aligned.m8n8.x4.shared.b16 {%0,%1,%2,%3}, [%4];" \
                 : "=r"(r0), "=r"(r1), "=r"(r2), "=r"(r3) : "r"(addr))

__device__ __forceinline__ void mma_tf32(float* d, const uint32_t* a, const uint32_t* b) {
    asm volatile(
        "mma.sync.aligned.m16n8k8.row.col.f32.tf32.tf32.f32 "
        "{%0,%1,%2,%3}, {%4,%5,%6,%7}, {%8,%9}, {%0,%1,%2,%3};"
        : "+f"(d[0]), "+f"(d[1]), "+f"(d[2]), "+f"(d[3])
        : "r"(a[0]), "r"(a[1]), "r"(a[2]), "r"(a[3]), "r"(b[0]), "r"(b[1]));
}
__device__ __forceinline__ void mma_bf16(float* d, const uint32_t* a, const uint32_t* b) {
    asm volatile(
        "mma.sync.aligned.m16n8k16.row.col.f32.bf16.bf16.f32 "
        "{%0,%1,%2,%3}, {%4,%5,%6,%7}, {%8,%9}, {%0,%1,%2,%3};"
        : "+f"(d[0]), "+f"(d[1]), "+f"(d[2]), "+f"(d[3])
        : "r"(a[0]), "r"(a[1]), "r"(a[2]), "r"(a[3]), "r"(b[0]), "r"(b[1]));
}

// Pack (v0, v1) into bf16x2 hi word and residual-lo word. v0 -> low half.
__device__ __forceinline__ void pack_hilo(float v0, float v1, uint32_t& hi, uint32_t& lo) {
    __nv_bfloat162 h2 = __floats2bfloat162_rn(v0, v1);
    uint32_t hw = *(uint32_t*)&h2;
    float h0 = __uint_as_float(hw << 16);
    float h1 = __uint_as_float(hw & 0xffff0000u);
    __nv_bfloat162 l2 = __floats2bfloat162_rn(v0 - h0, v1 - h1);
    hi = hw;
    lo = *(uint32_t*)&l2;
}

// ---------------------------------------------------------------------------
// tf32 GEMM (R8 record config): C[M,N] = A[M,K] @ BT[N,K]^T, both pre-rounded
// K-major. CTA 128x128, BK=32, 3-stage cp.async, 8 warps, 2 CTAs/SM,
// ldmatrix.x4 fragment loads.
// ---------------------------------------------------------------------------
#define BM 128
#define BN 128
#define BK 32
#define NSTG 3
#define PADW 36
#define ASTG (BM * PADW)
#define STGF (2 * BM * PADW)
#define GEMM_SMEM (NSTG * STGF * 4)

__global__ __launch_bounds__(256, 2) void gemm_mma(
    const float* __restrict__ A, const float* __restrict__ BT,
    float* __restrict__ C, int N, int K)
{
    extern __shared__ float sm[];
    const int tid = threadIdx.x;
    const int wid = tid >> 5, lane = tid & 31;
    const int wm = wid & 3, wn = wid >> 2;
    const int g = lane >> 2, c = lane & 3;
    const int bm = blockIdx.y * BM, bn = blockIdx.x * BN;
    const int NC = K / BK;

    const int mat = lane >> 3, r8 = lane & 7;
    const int a_row_l = wm * 32 + (mat & 1) * 8 + r8;
    const int a_k_l   = (mat >> 1) * 4;
    const int b_row_l = wn * 64 + (mat >> 1) * 8 + r8;
    const int b_k_l   = (mat & 1) * 4;

    float acc[2][8][4];
    #pragma unroll
    for (int mf = 0; mf < 2; mf++)
        #pragma unroll
        for (int nf = 0; nf < 8; nf++)
            #pragma unroll
            for (int i = 0; i < 4; i++) acc[mf][nf][i] = 0.f;

    auto load_stage = [&](int ct, int s) {
        float* base = sm + s * STGF;
        const int kt = ct * BK;
        #pragma unroll
        for (int h = 0; h < 4; h++) {
            int idx = tid + h * 256;
            int row = idx >> 3, c8 = idx & 7;
            CP_ASYNC16(smem_u32(base + row * PADW + c8 * 4),
                       A + (size_t)(bm + row) * K + kt + c8 * 4);
        }
        #pragma unroll
        for (int h = 0; h < 4; h++) {
            int idx = tid + h * 256;
            int row = idx >> 3, c8 = idx & 7;
            CP_ASYNC16(smem_u32(base + ASTG + row * PADW + c8 * 4),
                       BT + (size_t)(bn + row) * K + kt + c8 * 4);
        }
        CP_COMMIT();
    };

    load_stage(0, 0);
    load_stage(1, 1);

    for (int ct = 0; ct < NC; ct++) {
        CP_WAIT(1);
        __syncthreads();
        if (ct + 2 < NC) load_stage(ct + 2, (ct + 2) % NSTG);
        else CP_COMMIT();

        const float* As = sm + (ct % NSTG) * STGF;
        const float* Bs = As + ASTG;
        const uint32_t a_base = smem_u32(As + a_row_l * PADW + a_k_l);
        const uint32_t b_base = smem_u32(Bs + b_row_l * PADW + b_k_l);

        #pragma unroll
        for (int kk = 0; kk < 4; kk++) {
            uint32_t af[2][4], bf[8][2];
            #pragma unroll
            for (int mf = 0; mf < 2; mf++)
                LDSM_X4(af[mf][0], af[mf][1], af[mf][2], af[mf][3],
                        a_base + (mf * 16 * PADW + kk * 8) * 4);
            #pragma unroll
            for (int np = 0; np < 4; np++)
                LDSM_X4(bf[2 * np][0], bf[2 * np][1], bf[2 * np + 1][0], bf[2 * np + 1][1],
                        b_base + (np * 16 * PADW + kk * 8) * 4);
            #pragma unroll
            for (int mf = 0; mf < 2; mf++)
                #pragma unroll
                for (int nf = 0; nf < 8; nf++)
                    mma_tf32(acc[mf][nf], af[mf], bf[nf]);
        }
    }

    #pragma unroll
    for (int mf = 0; mf < 2; mf++) {
        #pragma unroll
        for (int nf = 0; nf < 8; nf++) {
            int row = bm + wm * 32 + mf * 16 + g;
            int col = bn + wn * 64 + nf * 8 + 2 * c;
            *(float2*)&C[(size_t)row * N + col] = make_float2(acc[mf][nf][0], acc[mf][nf][1]);
            *(float2*)&C[(size_t)(row + 8) * N + col] = make_float2(acc[mf][nf][2], acc[mf][nf][3]);
        }
    }
}

// ---------------------------------------------------------------------------
// Transpose + tf32 round / elementwise round
// ---------------------------------------------------------------------------
__global__ void transpose_rna(const float* __restrict__ src, float* __restrict__ dst,
                              int R, int C)
{
    __shared__ float t[32][33];
    const int bx = blockIdx.x * 32, by = blockIdx.y * 32;
    const int x = threadIdx.x, y0 = threadIdx.y;
    #pragma unroll
    for (int i = 0; i < 4; i++) {
        int r = by + y0 + i * 8;
        t[y0 + i * 8][x] = f32_to_tf32(src[(size_t)r * C + bx + x]);
    }
    __syncthreads();
    #pragma unroll
    for (int i = 0; i < 4; i++) {
        int c = bx + y0 + i * 8;
        dst[(size_t)c * R + by + x] = t[x][y0 + i * 8];
    }
}

__global__ void rna_copy(const float* __restrict__ src, float* __restrict__ dst, int n4)
{
    int i = blockIdx.x * blockDim.x + threadIdx.x;
    if (i < n4) {
        float4 v = ((const float4*)src)[i];
        v.x = f32_to_tf32(v.x); v.y = f32_to_tf32(v.y);
        v.z = f32_to_tf32(v.z); v.w = f32_to_tf32(v.w);
        ((float4*)dst)[i] = v;
    }
}

// ---------------------------------------------------------------------------
// RoPE
// ---------------------------------------------------------------------------
__global__ void rope_kernel(const float* __restrict__ cosp,
                            const float* __restrict__ sinp)
{
    const int l = blockIdx.x;
    const int y = blockIdx.y;
    const int t = threadIdx.x;
    const int off = (y < NH) ? y * HDIM : KOFF + (y - NH) * HDIM;
    const size_t base = (size_t)l * QKVN + off;

    float v  = g_qkv[base + t];
    int pj   = (t < 32) ? t + 32 : t - 32;
    float pv = g_qkv[base + pj];
    float cc = cosp[l * 64 + t];
    float ss = sinp[l * 64 + t];
    float o = (t < 32) ? fmaf(v, cc, -pv * ss) : fmaf(v, cc, pv * ss);
    __syncthreads();
    g_qkv[base + t] = o;
}

// ---------------------------------------------------------------------------
// Pack K (post-RoPE): g_kp[kvh][l][hi j | lo 64+j]
// 256-thread blocks, 4 seq rows per block (was 64-thread blocks: launch-bound).
// ---------------------------------------------------------------------------
__global__ void pack_k_kernel()
{
    const int tid = threadIdx.x;
    const int l = blockIdx.x * 4 + (tid >> 6);
    const int kvh = blockIdx.y;
    const int j = tid & 63;
    const float* src = &g_qkv[(size_t)l * QKVN + KOFF + kvh * HDIM];
    uint32_t hi, lo;
    pack_hilo(src[2 * j], src[2 * j + 1], hi, lo);
    uint32_t* dst = &g_kp[((size_t)kvh * LSEQ + l) * 128];
    dst[j] = hi;
    dst[64 + j] = lo;
}

// ---------------------------------------------------------------------------
// Pack V transposed: g_vtp[kvh][d][hi kp | lo 1024+kp]
// ---------------------------------------------------------------------------
__global__ void pack_vt_kernel()
{
    __shared__ float sf[128][66];
    const int l0 = blockIdx.x * 64, kvh = blockIdx.y;
    const int tid = threadIdx.x;

    #pragma unroll
    for (int i = 0; i < 32; i++) {
        int idx = tid + i * 256;
        int ll = idx >> 7, d = idx & 127;
        sf[d][ll] = g_qkv[(size_t)(l0 + ll) * QKVN + VOFF + kvh * HDIM + d];
    }
    __syncthreads();

    const int kp_l = tid & 31;
    #pragma unroll
    for (int i = 0; i < 16; i++) {
        int d = (tid >> 5) + i * 8;
        uint32_t hi, lo;
        pack_hilo(sf[d][2 * kp_l], sf[d][2 * kp_l + 1], hi, lo);
        size_t base = ((size_t)kvh * HDIM + d) * 2048 + (l0 >> 1) + kp_l;
        g_vtp[base] = hi;
        g_vtp[base + 1024] = lo;
    }
}

// ---------------------------------------------------------------------------
// Flash attention (R8 record config): bf16 hi/lo split mma; 256 threads,
// 8 warps x 16 q-rows; K/V via cp.async pre-packed.
// ---------------------------------------------------------------------------
#define QW 68
#define VW 44
#define QHI_OFF 0
#define QLO_OFF (128 * QW)
#define KBUF_OFF 17408
#define VTH_OFF (KBUF_OFF + 2 * 8704)
#define VTL_OFF (VTH_OFF + 128 * VW)
#define ATT_SMEM_WORDS (VTL_OFF + 128 * VW)
#define ATT_SMEM_BYTES (ATT_SMEM_WORDS * 4)

__global__ __launch_bounds__(256, 1) void attn_kernel()
{
    extern __shared__ uint32_t sw[];

    const int qt = (int)gridDim.x - 1 - (int)blockIdx.x;
    const int h  = blockIdx.y;
    const int kvh = h >> 2;
    const int qoff = h * HDIM;
    const int qbase = qt * 128;

    const int tid = threadIdx.x;
    const int w = tid >> 5, lane = tid & 31;
    const int g = lane >> 2, cc = lane & 3;

    #pragma unroll
    for (int i = 0; i < 16; i++) {
        int idx = tid + i * 256;
        int row = idx >> 5, c4 = idx & 31;
        float4 v = *(const float4*)&g_qkv[(size_t)(qbase + row) * QKVN + qoff + c4 * 4];
        uint32_t h0, l0, h1, l1;
        pack_hilo(v.x, v.y, h0, l0);
        pack_hilo(v.z, v.w, h1, l1);
        int wo = row * QW + c4 * 2;
        sw[QHI_OFF + wo] = h0; sw[QHI_OFF + wo + 1] = h1;
        sw[QLO_OFF + wo] = l0; sw[QLO_OFF + wo + 1] = l1;
    }

    auto load_k = [&](int kb, int buf) {
        const uint32_t* src0 = &g_kp[((size_t)kvh * LSEQ + kb) * 128];
        const int base = KBUF_OFF + buf * 8704;
        #pragma unroll
        for (int i = 0; i < 8; i++) {
            int idx = tid + i * 256;
            int half = idx >> 10;
            int r = (idx >> 4) & 63;
            int ch = idx & 15;
            int woff = base + half * 4352 + r * QW + ch * 4;
            CP_ASYNC16(smem_u32(sw + woff), src0 + (size_t)r * 128 + half * 64 + ch * 4);
        }
        CP_COMMIT();
    };
    auto load_v = [&](int kb) {
        const uint32_t* src0 = &g_vtp[(size_t)kvh * HDIM * 2048 + (kb >> 1)];
        #pragma unroll
        for (int i = 0; i < 8; i++) {
            int idx = tid + i * 256;
            int half = idx >> 10;
            int d = (idx >> 3) & 127;
            int ch = idx & 7;
            int woff = (half ? VTL_OFF : VTH_OFF) + d * VW + ch * 4;
            CP_ASYNC16(smem_u32(sw + woff), src0 + (size_t)d * 2048 + half * 1024 + ch * 4);
        }
        CP_COMMIT();
    };

    float m0 = -1e30f, m1 = -1e30f, l0s = 0.f, l1s = 0.f;
    float o[16][4];
    #pragma unroll
    for (int j = 0; j < 16; j++)
        #pragma unroll
        for (int i = 0; i < 4; i++) o[j][i] = 0.f;

    const int r0 = qbase + w * 16 + g;
    const int r1 = r0 + 8;
    const float sl2e = ATT_SCALE * LOG2E;
    const int nkt = 2 * qt + 2;

    load_k(0, 0);

    for (int kt = 0; kt < nkt; kt++) {
        const int kb = kt * 64;
        const int kbase = KBUF_OFF + (kt & 1) * 8704;

        __syncthreads();
        load_v(kb);
        const bool more = (kt + 1 < nkt);
        if (more) load_k(kb + 64, (kt + 1) & 1);

        if (more) CP_WAIT(2); else CP_WAIT(1);
        __syncthreads();

        float s[8][4];
        #pragma unroll
        for (int j = 0; j < 8; j++)
            #pragma unroll
            for (int i = 0; i < 4; i++) s[j][i] = 0.f;

        #pragma unroll
        for (int kk = 0; kk < 8; kk++) {
            uint32_t ah[4], al[4];
            int ab = (w * 16 + g) * QW + kk * 8 + cc;
            ah[0] = sw[QHI_OFF + ab];              al[0] = sw[QLO_OFF + ab];
            ah[1] = sw[QHI_OFF + ab + 8 * QW];     al[1] = sw[QLO_OFF + ab + 8 * QW];
            ah[2] = sw[QHI_OFF + ab + 4];          al[2] = sw[QLO_OFF + ab + 4];
            ah[3] = sw[QHI_OFF + ab + 8 * QW + 4]; al[3] = sw[QLO_OFF + ab + 8 * QW + 4];
            #pragma unroll
            for (int j = 0; j < 8; j++) {
                uint32_t bh[2], bl[2];
                int bb = kbase + (j * 8 + g) * QW + kk * 8 + cc;
                bh[0] = sw[bb];        bh[1] = sw[bb + 4];
                bl[0] = sw[bb + 4352]; bl[1] = sw[bb + 4352 + 4];
                mma_bf16(s[j], ah, bh);
                mma_bf16(s[j], al, bh);
                mma_bf16(s[j], ah, bl);
            }
        }

        if (kt >= 2 * qt) {
            #pragma unroll
            for (int j = 0; j < 8; j++) {
                int colb = kb + j * 8 + 2 * cc;
                if (colb > r0)     s[j][0] = -1e30f;
                if (colb + 1 > r0) s[j][1] = -1e30f;
                if (colb > r1)     s[j][2] = -1e30f;
                if (colb + 1 > r1) s[j][3] = -1e30f;
            }
        }

        float mx0 = -1e30f, mx1 = -1e30f;
        #pragma unroll
        for (int j = 0; j < 8; j++) {
            mx0 = fmaxf(mx0, fmaxf(s[j][0], s[j][1]));
            mx1 = fmaxf(mx1, fmaxf(s[j][2], s[j][3]));
        }
        mx0 = fmaxf(mx0, __shfl_xor_sync(0xffffffffu, mx0, 1));
        mx0 = fmaxf(mx0, __shfl_xor_sync(0xffffffffu, mx0, 2));
        mx1 = fmaxf(mx1, __shfl_xor_sync(0xffffffffu, mx1, 1));
        mx1 = fmaxf(mx1, __shfl_xor_sync(0xffffffffu, mx1, 2));

        float mn0 = fmaxf(m0, mx0), mn1 = fmaxf(m1, mx1);
        float corr0 = exp2f((m0 - mn0) * sl2e);
        float corr1 = exp2f((m1 - mn1) * sl2e);
        m0 = mn0; m1 = mn1;

        uint32_t Ph0[8], Pl0[8], Ph1[8], Pl1[8];
        float sum0 = 0.f, sum1 = 0.f;
        #pragma unroll
        for (int j = 0; j < 8; j++) {
            float p0 = exp2f((s[j][0] - m0) * sl2e);
            float p1 = exp2f((s[j][1] - m0) * sl2e);
            float p2 = exp2f((s[j][2] - m1) * sl2e);
            float p3 = exp2f((s[j][3] - m1) * sl2e);
            sum0 += p0 + p1; sum1 += p2 + p3;
            pack_hilo(p0, p1, Ph0[j], Pl0[j]);
            pack_hilo(p2, p3, Ph1[j], Pl1[j]);
        }
        sum0 += __shfl_xor_sync(0xffffffffu, sum0, 1);
        sum0 += __shfl_xor_sync(0xffffffffu, sum0, 2);
        sum1 += __shfl_xor_sync(0xffffffffu, sum1, 1);
        sum1 += __shfl_xor_sync(0xffffffffu, sum1, 2);
        l0s = l0s * corr0 + sum0;
        l1s = l1s * corr1 + sum1;

        #pragma unroll
        for (int j = 0; j < 16; j++) {
            o[j][0] *= corr0; o[j][1] *= corr0;
            o[j][2] *= corr1; o[j][3] *= corr1;
        }

        if (more) CP_WAIT(1); else CP_WAIT(0);
        __syncthreads();

        #pragma unroll
        for (int kk = 0; kk < 4; kk++) {
            uint32_t ah[4] = {Ph0[2 * kk], Ph1[2 * kk], Ph0[2 * kk + 1], Ph1[2 * kk + 1]};
            uint32_t al[4] = {Pl0[2 * kk], Pl1[2 * kk], Pl0[2 * kk + 1], Pl1[2 * kk + 1]};
            #pragma unroll
            for (int jn = 0; jn < 16; jn++) {
                uint32_t bh[2], bl[2];
                int vb = (jn * 8 + g) * VW + kk * 8 + cc;
                bh[0] = sw[VTH_OFF + vb]; bh[1] = sw[VTH_OFF + vb + 4];
                bl[0] = sw[VTL_OFF + vb]; bl[1] = sw[VTL_OFF + vb + 4];
                mma_bf16(o[jn], ah, bh);
                mma_bf16(o[jn], al, bh);
                mma_bf16(o[jn], ah, bl);
            }
        }
    }

    float li0 = 1.0f / l0s, li1 = 1.0f / l1s;
    #pragma unroll
    for (int jn = 0; jn < 16; jn++) {
        int col = h * HDIM + jn * 8 + 2 * cc;
        *(float2*)&g_o[(size_t)r0 * DMODEL + col] =
            make_float2(f32_to_tf32(o[jn][0] * li0), f32_to_tf32(o[jn][1] * li0));
        *(float2*)&g_o[(size_t)r1 * DMODEL + col] =
            make_float2(f32_to_tf32(o[jn][2] * li1), f32_to_tf32(o[jn][3] * li1));
    }
}

// ---------------------------------------------------------------------------
// Launch (R8 structure)
// ---------------------------------------------------------------------------
extern "C" void kernel_launch(void* const* d_in, const int* in_sizes, int n_in,
                              void* d_out, int out_size)
{
    const float* x     = (const float*)d_in[0];
    const float* cosp  = (const float*)d_in[2];
    const float* sinp  = (const float*)d_in[3];
    const float* w_qkv = (const float*)d_in[4];
    const float* w_o   = (const float*)d_in[5];
    float* out = (float*)d_out;

    float *qkv_p, *o_p, *xr_p, *wqkvT_p, *woT_p;
    cudaGetSymbolAddress((void**)&qkv_p, g_qkv);
    cudaGetSymbolAddress((void**)&o_p, g_o);
    cudaGetSymbolAddress((void**)&xr_p, g_xr);
    cudaGetSymbolAddress((void**)&wqkvT_p, g_wqkvT);
    cudaGetSymbolAddress((void**)&woT_p, g_woT);

    cudaFuncSetAttribute(gemm_mma, cudaFuncAttributeMaxDynamicSharedMemorySize, GEMM_SMEM);
    cudaFuncSetAttribute(attn_kernel, cudaFuncAttributeMaxDynamicSharedMemorySize, ATT_SMEM_BYTES);

    // 0. tf32-round inputs / transpose weights to K-major
    rna_copy<<<(LSEQ * DMODEL / 4 + 255) / 256, 256>>>(x, xr_p, LSEQ * DMODEL / 4);
    transpose_rna<<<dim3(QKVN / 32, DMODEL / 32), dim3(32, 8)>>>(w_qkv, wqkvT_p, DMODEL, QKVN);
    transpose_rna<<<dim3(DMODEL / 32, DMODEL / 32), dim3(32, 8)>>>(w_o, woT_p, DMODEL, DMODEL);

    // 1. QKV projection (tf32 mma, ldmatrix frags)
    gemm_mma<<<dim3(QKVN / BN, LSEQ / BM), 256, GEMM_SMEM>>>(xr_p, wqkvT_p, qkv_p, QKVN, DMODEL);

    // 2. RoPE
    rope_kernel<<<dim3(LSEQ, NH + NKV), 64>>>(cosp, sinp);

    // 3. Pack K / V^T to bf16 hi/lo once
    pack_k_kernel<<<dim3(LSEQ / 4, NKV), 256>>>();
    pack_vt_kernel<<<dim3(LSEQ / 64, NKV), 256>>>();

    // 4. Flash attention
    attn_kernel<<<dim3(LSEQ / 128, NH), 256, ATT_SMEM_BYTES>>>();

    // 5. Output projection (tf32 mma, ldmatrix frags)
    gemm_mma<<<dim3(DMODEL / BN, LSEQ / BM), 256, GEMM_SMEM>>>(o_p, woT_p, out, DMODEL, DMODEL);
}

// round 17
// speedup vs baseline: 1.2248x; 1.1386x over previous
#include <cuda_runtime.h>
#include <cuda_bf16.h>
#include <math.h>
#include <stdint.h>

// Problem constants
#define LSEQ 2048
#define DMODEL 4096
#define NH 32
#define NKV 8
#define HDIM 128
#define QKVN 6144            // 32*128 + 2*8*128
#define KOFF 4096
#define VOFF 5120
#define ATT_SCALE 0.08838834764831843f
#define LOG2E 1.44269504089f

// Scratch (no cudaMalloc allowed)
__device__ float g_qkv[(size_t)LSEQ * QKVN];       // 50 MB
__device__ float g_o[(size_t)LSEQ * DMODEL];       // 33 MB
__device__ float g_xr[(size_t)LSEQ * DMODEL];      // 33 MB (tf32-rounded x)
__device__ float g_wqkvT[(size_t)QKVN * DMODEL];   // 100 MB
__device__ float g_woT[(size_t)DMODEL * DMODEL];   // 67 MB
// Packed bf16 hi/lo K and V^T (computed once post-RoPE, shared by all attn CTAs)
__device__ uint32_t g_kp[(size_t)NKV * LSEQ * 128];      // [kvh][l][hi 0..63 | lo 64..127]
__device__ uint32_t g_vtp[(size_t)NKV * HDIM * 2048];    // [kvh][d][hi kp 0..1023 | lo 1024..2047]

// ---------------------------------------------------------------------------
// Helpers
// ---------------------------------------------------------------------------
__device__ __forceinline__ uint32_t smem_u32(const void* p) {
    uint32_t a;
    asm("{ .reg .u64 t; cvta.to.shared.u64 t, %1; cvt.u32.u64 %0, t; }" : "=r"(a) : "l"(p));
    return a;
}
__device__ __forceinline__ float f32_to_tf32(float v) {
    uint32_t o;
    asm("cvt.rna.tf32.f32 %0, %1;" : "=r"(o) : "f"(v));
    return __uint_as_float(o);
}
#define CP_ASYNC16(dst, src) \
    asm volatile("cp.async.cg.shared.global [%0], [%1], 16;" :: "r"(dst), "l"(src))
#define CP_COMMIT() asm volatile("cp.async.commit_group;")
#define CP_WAIT(n)  asm volatile("cp.async.wait_group %0;" :: "n"(n))

#define MBAR_INIT(a, c) \
    asm volatile("mbarrier.init.shared.b64 [%0], %1;" :: "r"(a), "r"(c) : "memory")
#define MBAR_ARRIVE(a) \
    asm volatile("mbarrier.arrive.shared.b64 _, [%0];" :: "r"(a) : "memory")
// .noinc: arrival counts against the fixed init count (default variant would
// bump the pending count first -> net-zero progress -> deadlock, the R16 bug).
#define CP_MBAR_ARRIVE_NOINC(a) \
    asm volatile("cp.async.mbarrier.arrive.noinc.shared.b64 [%0];" :: "r"(a) : "memory")

__device__ __forceinline__ void mbar_wait(uint32_t addr, uint32_t parity) {
    uint32_t done = 0;
    while (!done) {
        asm volatile(
            "{\n\t.reg .pred p;\n\t"
            "mbarrier.try_wait.parity.shared.b64 p, [%1], %2, 0x989680;\n\t"
            "selp.b32 %0, 1, 0, p;\n\t}"
            : "=r"(done) : "r"(addr), "r"(parity) : "memory");
    }
}

#define LDSM_X4(r0, r1, r2, r3, addr) \
    asm volatile("ldmatrix.sync.aligned.m8n8.x4.shared.b16 {%0,%1,%2,%3}, [%4];" \
                 : "=r"(r0), "=r"(r1), "=r"(r2), "=r"(r3) : "r"(addr))

__device__ __forceinline__ void mma_tf32(float* d, const uint32_t* a, const uint32_t* b) {
    asm volatile(
        "mma.sync.aligned.m16n8k8.row.col.f32.tf32.tf32.f32 "
        "{%0,%1,%2,%3}, {%4,%5,%6,%7}, {%8,%9}, {%0,%1,%2,%3};"
        : "+f"(d[0]), "+f"(d[1]), "+f"(d[2]), "+f"(d[3])
        : "r"(a[0]), "r"(a[1]), "r"(a[2]), "r"(a[3]), "r"(b[0]), "r"(b[1]));
}
__device__ __forceinline__ void mma_bf16(float* d, const uint32_t* a, const uint32_t* b) {
    asm volatile(
        "mma.sync.aligned.m16n8k16.row.col.f32.bf16.bf16.f32 "
        "{%0,%1,%2,%3}, {%4,%5,%6,%7}, {%8,%9}, {%0,%1,%2,%3};"
        : "+f"(d[0]), "+f"(d[1]), "+f"(d[2]), "+f"(d[3])
        : "r"(a[0]), "r"(a[1]), "r"(a[2]), "r"(a[3]), "r"(b[0]), "r"(b[1]));
}

// Pack (v0, v1) into bf16x2 hi word and residual-lo word. v0 -> low half.
__device__ __forceinline__ void pack_hilo(float v0, float v1, uint32_t& hi, uint32_t& lo) {
    __nv_bfloat162 h2 = __floats2bfloat162_rn(v0, v1);
    uint32_t hw = *(uint32_t*)&h2;
    float h0 = __uint_as_float(hw << 16);
    float h1 = __uint_as_float(hw & 0xffff0000u);
    __nv_bfloat162 l2 = __floats2bfloat162_rn(v0 - h0, v1 - h1);
    hi = hw;
    lo = *(uint32_t*)&l2;
}

// ---------------------------------------------------------------------------
// tf32 GEMM, mbarrier-pipelined: per stage s, full[s] (count 256, signaled via
// cp.async.mbarrier.arrive.noinc) / empty[s] (count 8, one arrive per warp).
// Warps free-run up to pipeline depth. CTA 128x128, BK=32, 3 stages, 8 warps,
// 2 CTAs/SM, ldmatrix.x4 fragment loads.
// ---------------------------------------------------------------------------
#define BM 128
#define BN 128
#define BK 32
#define NSTG 3
#define PADW 36
#define ASTG (BM * PADW)
#define STGF (2 * BM * PADW)
#define GEMM_SMEM (NSTG * STGF * 4)

__global__ __launch_bounds__(256, 2) void gemm_mma(
    const float* __restrict__ A, const float* __restrict__ BT,
    float* __restrict__ C, int N, int K)
{
    extern __shared__ float sm[];
    __shared__ __align__(8) unsigned long long s_mbar[2 * NSTG];  // full 0..2, empty 3..5

    const int tid = threadIdx.x;
    const int wid = tid >> 5, lane = tid & 31;
    const int wm = wid & 3, wn = wid >> 2;
    const int g = lane >> 2, c = lane & 3;
    const int bm = blockIdx.y * BM, bn = blockIdx.x * BN;
    const int NC = K / BK;

    const uint32_t mb0 = smem_u32(&s_mbar[0]);
    if (tid == 0) {
        #pragma unroll
        for (int s = 0; s < NSTG; s++) {
            MBAR_INIT(mb0 + s * 8, 256);              // full[s]
            MBAR_INIT(mb0 + (NSTG + s) * 8, 8);       // empty[s]
        }
    }
    __syncthreads();

    const int mat = lane >> 3, r8 = lane & 7;
    const int a_row_l = wm * 32 + (mat & 1) * 8 + r8;
    const int a_k_l   = (mat >> 1) * 4;
    const int b_row_l = wn * 64 + (mat >> 1) * 8 + r8;
    const int b_k_l   = (mat & 1) * 4;

    float acc[2][8][4];
    #pragma unroll
    for (int mf = 0; mf < 2; mf++)
        #pragma unroll
        for (int nf = 0; nf < 8; nf++)
            #pragma unroll
            for (int i = 0; i < 4; i++) acc[mf][nf][i] = 0.f;

    // fill chunk n into stage n%3 (all 256 threads participate)
    auto fill = [&](int n) {
        const int s = n % NSTG;
        const int f = n / NSTG;
        const uint32_t par = (f == 0) ? 1u : (uint32_t)((f - 1) & 1);
        mbar_wait(mb0 + (NSTG + s) * 8, par);         // stage free?
        float* base = sm + s * STGF;
        const int kt = n * BK;
        #pragma unroll
        for (int h = 0; h < 4; h++) {
            int idx = tid + h * 256;
            int row = idx >> 3, c8 = idx & 7;
            CP_ASYNC16(smem_u32(base + row * PADW + c8 * 4),
                       A + (size_t)(bm + row) * K + kt + c8 * 4);
        }
        #pragma unroll
        for (int h = 0; h < 4; h++) {
            int idx = tid + h * 256;
            int row = idx >> 3, c8 = idx & 7;
            CP_ASYNC16(smem_u32(base + ASTG + row * PADW + c8 * 4),
                       BT + (size_t)(bn + row) * K + kt + c8 * 4);
        }
        CP_MBAR_ARRIVE_NOINC(mb0 + s * 8);            // async arrive when done
    };

    fill(0);
    fill(1);

    for (int ct = 0; ct < NC; ct++) {
        const int s = ct % NSTG;
        mbar_wait(mb0 + s * 8, (uint32_t)((ct / NSTG) & 1));   // stage full?

        const float* As = sm + s * STGF;
        const float* Bs = As + ASTG;
        const uint32_t a_base = smem_u32(As + a_row_l * PADW + a_k_l);
        const uint32_t b_base = smem_u32(Bs + b_row_l * PADW + b_k_l);

        #pragma unroll
        for (int kk = 0; kk < 4; kk++) {
            uint32_t af[2][4], bf[8][2];
            #pragma unroll
            for (int mf = 0; mf < 2; mf++)
                LDSM_X4(af[mf][0], af[mf][1], af[mf][2], af[mf][3],
                        a_base + (mf * 16 * PADW + kk * 8) * 4);
            #pragma unroll
            for (int np = 0; np < 4; np++)
                LDSM_X4(bf[2 * np][0], bf[2 * np][1], bf[2 * np + 1][0], bf[2 * np + 1][1],
                        b_base + (np * 16 * PADW + kk * 8) * 4);
            #pragma unroll
            for (int mf = 0; mf < 2; mf++)
                #pragma unroll
                for (int nf = 0; nf < 8; nf++)
                    mma_tf32(acc[mf][nf], af[mf], bf[nf]);
        }

        // LDSM completed before mma consumed its outputs -> stage reads retired
        if (lane == 0) MBAR_ARRIVE(mb0 + (NSTG + s) * 8);

        if (ct + 2 < NC) fill(ct + 2);
    }

    #pragma unroll
    for (int mf = 0; mf < 2; mf++) {
        #pragma unroll
        for (int nf = 0; nf < 8; nf++) {
            int row = bm + wm * 32 + mf * 16 + g;
            int col = bn + wn * 64 + nf * 8 + 2 * c;
            *(float2*)&C[(size_t)row * N + col] = make_float2(acc[mf][nf][0], acc[mf][nf][1]);
            *(float2*)&C[(size_t)(row + 8) * N + col] = make_float2(acc[mf][nf][2], acc[mf][nf][3]);
        }
    }
}

// ---------------------------------------------------------------------------
// Transpose + tf32 round / elementwise round
// ---------------------------------------------------------------------------
__global__ void transpose_rna(const float* __restrict__ src, float* __restrict__ dst,
                              int R, int C)
{
    __shared__ float t[32][33];
    const int bx = blockIdx.x * 32, by = blockIdx.y * 32;
    const int x = threadIdx.x, y0 = threadIdx.y;
    #pragma unroll
    for (int i = 0; i < 4; i++) {
        int r = by + y0 + i * 8;
        t[y0 + i * 8][x] = f32_to_tf32(src[(size_t)r * C + bx + x]);
    }
    __syncthreads();
    #pragma unroll
    for (int i = 0; i < 4; i++) {
        int c = bx + y0 + i * 8;
        dst[(size_t)c * R + by + x] = t[x][y0 + i * 8];
    }
}

__global__ void rna_copy(const float* __restrict__ src, float* __restrict__ dst, int n4)
{
    int i = blockIdx.x * blockDim.x + threadIdx.x;
    if (i < n4) {
        float4 v = ((const float4*)src)[i];
        v.x = f32_to_tf32(v.x); v.y = f32_to_tf32(v.y);
        v.z = f32_to_tf32(v.z); v.w = f32_to_tf32(v.w);
        ((float4*)dst)[i] = v;
    }
}

// ---------------------------------------------------------------------------
// RoPE: 256-thread blocks, 4 (l,y) units per block
// ---------------------------------------------------------------------------
__global__ void rope_kernel(const float* __restrict__ cosp,
                            const float* __restrict__ sinp)
{
    const int tid = threadIdx.x;
    const int l = blockIdx.x;
    const int y = blockIdx.y * 4 + (tid >> 6);
    const int t = tid & 63;
    const int off = (y < NH) ? y * HDIM : KOFF + (y - NH) * HDIM;
    const size_t base = (size_t)l * QKVN + off;

    float v  = g_qkv[base + t];
    int pj   = (t < 32) ? t + 32 : t - 32;
    float pv = g_qkv[base + pj];
    float cc = cosp[l * 64 + t];
    float ss = sinp[l * 64 + t];
    float o = (t < 32) ? fmaf(v, cc, -pv * ss) : fmaf(v, cc, pv * ss);
    __syncthreads();
    g_qkv[base + t] = o;
}

// ---------------------------------------------------------------------------
// Pack K (post-RoPE): g_kp[kvh][l][hi j | lo 64+j], 256-thread blocks
// ---------------------------------------------------------------------------
__global__ void pack_k_kernel()
{
    const int tid = threadIdx.x;
    const int l = blockIdx.x * 4 + (tid >> 6);
    const int kvh = blockIdx.y;
    const int j = tid & 63;
    const float* src = &g_qkv[(size_t)l * QKVN + KOFF + kvh * HDIM];
    uint32_t hi, lo;
    pack_hilo(src[2 * j], src[2 * j + 1], hi, lo);
    uint32_t* dst = &g_kp[((size_t)kvh * LSEQ + l) * 128];
    dst[j] = hi;
    dst[64 + j] = lo;
}

// ---------------------------------------------------------------------------
// Pack V transposed: g_vtp[kvh][d][hi kp | lo 1024+kp]
// ---------------------------------------------------------------------------
__global__ void pack_vt_kernel()
{
    __shared__ float sf[128][66];
    const int l0 = blockIdx.x * 64, kvh = blockIdx.y;
    const int tid = threadIdx.x;

    #pragma unroll
    for (int i = 0; i < 32; i++) {
        int idx = tid + i * 256;
        int ll = idx >> 7, d = idx & 127;
        sf[d][ll] = g_qkv[(size_t)(l0 + ll) * QKVN + VOFF + kvh * HDIM + d];
    }
    __syncthreads();

    const int kp_l = tid & 31;
    #pragma unroll
    for (int i = 0; i < 16; i++) {
        int d = (tid >> 5) + i * 8;
        uint32_t hi, lo;
        pack_hilo(sf[d][2 * kp_l], sf[d][2 * kp_l + 1], hi, lo);
        size_t base = ((size_t)kvh * HDIM + d) * 2048 + (l0 >> 1) + kp_l;
        g_vtp[base] = hi;
        g_vtp[base + 1024] = lo;
    }
}

// ---------------------------------------------------------------------------
// Flash attention (R15 record config): bf16 hi/lo split mma; 256 threads,
// 8 warps x 16 q-rows; K/V via cp.async pre-packed.
// ---------------------------------------------------------------------------
#define QW 68
#define VW 44
#define QHI_OFF 0
#define QLO_OFF (128 * QW)
#define KBUF_OFF 17408
#define VTH_OFF (KBUF_OFF + 2 * 8704)
#define VTL_OFF (VTH_OFF + 128 * VW)
#define ATT_SMEM_WORDS (VTL_OFF + 128 * VW)
#define ATT_SMEM_BYTES (ATT_SMEM_WORDS * 4)

__global__ __launch_bounds__(256, 1) void attn_kernel()
{
    extern __shared__ uint32_t sw[];

    const int qt = (int)gridDim.x - 1 - (int)blockIdx.x;
    const int h  = blockIdx.y;
    const int kvh = h >> 2;
    const int qoff = h * HDIM;
    const int qbase = qt * 128;

    const int tid = threadIdx.x;
    const int w = tid >> 5, lane = tid & 31;
    const int g = lane >> 2, cc = lane & 3;

    #pragma unroll
    for (int i = 0; i < 16; i++) {
        int idx = tid + i * 256;
        int row = idx >> 5, c4 = idx & 31;
        float4 v = *(const float4*)&g_qkv[(size_t)(qbase + row) * QKVN + qoff + c4 * 4];
        uint32_t h0, l0, h1, l1;
        pack_hilo(v.x, v.y, h0, l0);
        pack_hilo(v.z, v.w, h1, l1);
        int wo = row * QW + c4 * 2;
        sw[QHI_OFF + wo] = h0; sw[QHI_OFF + wo + 1] = h1;
        sw[QLO_OFF + wo] = l0; sw[QLO_OFF + wo + 1] = l1;
    }

    auto load_k = [&](int kb, int buf) {
        const uint32_t* src0 = &g_kp[((size_t)kvh * LSEQ + kb) * 128];
        const int base = KBUF_OFF + buf * 8704;
        #pragma unroll
        for (int i = 0; i < 8; i++) {
            int idx = tid + i * 256;
            int half = idx >> 10;
            int r = (idx >> 4) & 63;
            int ch = idx & 15;
            int woff = base + half * 4352 + r * QW + ch * 4;
            CP_ASYNC16(smem_u32(sw + woff), src0 + (size_t)r * 128 + half * 64 + ch * 4);
        }
        CP_COMMIT();
    };
    auto load_v = [&](int kb) {
        const uint32_t* src0 = &g_vtp[(size_t)kvh * HDIM * 2048 + (kb >> 1)];
        #pragma unroll
        for (int i = 0; i < 8; i++) {
            int idx = tid + i * 256;
            int half = idx >> 10;
            int d = (idx >> 3) & 127;
            int ch = idx & 7;
            int woff = (half ? VTL_OFF : VTH_OFF) + d * VW + ch * 4;
            CP_ASYNC16(smem_u32(sw + woff), src0 + (size_t)d * 2048 + half * 1024 + ch * 4);
        }
        CP_COMMIT();
    };

    float m0 = -1e30f, m1 = -1e30f, l0s = 0.f, l1s = 0.f;
    float o[16][4];
    #pragma unroll
    for (int j = 0; j < 16; j++)
        #pragma unroll
        for (int i = 0; i < 4; i++) o[j][i] = 0.f;

    const int r0 = qbase + w * 16 + g;
    const int r1 = r0 + 8;
    const float sl2e = ATT_SCALE * LOG2E;
    const int nkt = 2 * qt + 2;

    load_k(0, 0);

    for (int kt = 0; kt < nkt; kt++) {
        const int kb = kt * 64;
        const int kbase = KBUF_OFF + (kt & 1) * 8704;

        __syncthreads();
        load_v(kb);
        const bool more = (kt + 1 < nkt);
        if (more) load_k(kb + 64, (kt + 1) & 1);

        if (more) CP_WAIT(2); else CP_WAIT(1);
        __syncthreads();

        float s[8][4];
        #pragma unroll
        for (int j = 0; j < 8; j++)
            #pragma unroll
            for (int i = 0; i < 4; i++) s[j][i] = 0.f;

        #pragma unroll
        for (int kk = 0; kk < 8; kk++) {
            uint32_t ah[4], al[4];
            int ab = (w * 16 + g) * QW + kk * 8 + cc;
            ah[0] = sw[QHI_OFF + ab];              al[0] = sw[QLO_OFF + ab];
            ah[1] = sw[QHI_OFF + ab + 8 * QW];     al[1] = sw[QLO_OFF + ab + 8 * QW];
            ah[2] = sw[QHI_OFF + ab + 4];          al[2] = sw[QLO_OFF + ab + 4];
            ah[3] = sw[QHI_OFF + ab + 8 * QW + 4]; al[3] = sw[QLO_OFF + ab + 8 * QW + 4];
            #pragma unroll
            for (int j = 0; j < 8; j++) {
                uint32_t bh[2], bl[2];
                int bb = kbase + (j * 8 + g) * QW + kk * 8 + cc;
                bh[0] = sw[bb];        bh[1] = sw[bb + 4];
                bl[0] = sw[bb + 4352]; bl[1] = sw[bb + 4352 + 4];
                mma_bf16(s[j], ah, bh);
                mma_bf16(s[j], al, bh);
                mma_bf16(s[j], ah, bl);
            }
        }

        if (kt >= 2 * qt) {
            #pragma unroll
            for (int j = 0; j < 8; j++) {
                int colb = kb + j * 8 + 2 * cc;
                if (colb > r0)     s[j][0] = -1e30f;
                if (colb + 1 > r0) s[j][1] = -1e30f;
                if (colb > r1)     s[j][2] = -1e30f;
                if (colb + 1 > r1) s[j][3] = -1e30f;
            }
        }

        float mx0 = -1e30f, mx1 = -1e30f;
        #pragma unroll
        for (int j = 0; j < 8; j++) {
            mx0 = fmaxf(mx0, fmaxf(s[j][0], s[j][1]));
            mx1 = fmaxf(mx1, fmaxf(s[j][2], s[j][3]));
        }
        mx0 = fmaxf(mx0, __shfl_xor_sync(0xffffffffu, mx0, 1));
        mx0 = fmaxf(mx0, __shfl_xor_sync(0xffffffffu, mx0, 2));
        mx1 = fmaxf(mx1, __shfl_xor_sync(0xffffffffu, mx1, 1));
        mx1 = fmaxf(mx1, __shfl_xor_sync(0xffffffffu, mx1, 2));

        float mn0 = fmaxf(m0, mx0), mn1 = fmaxf(m1, mx1);
        float corr0 = exp2f((m0 - mn0) * sl2e);
        float corr1 = exp2f((m1 - mn1) * sl2e);
        m0 = mn0; m1 = mn1;

        uint32_t Ph0[8], Pl0[8], Ph1[8], Pl1[8];
        float sum0 = 0.f, sum1 = 0.f;
        #pragma unroll
        for (int j = 0; j < 8; j++) {
            float p0 = exp2f((s[j][0] - m0) * sl2e);
            float p1 = exp2f((s[j][1] - m0) * sl2e);
            float p2 = exp2f((s[j][2] - m1) * sl2e);
            float p3 = exp2f((s[j][3] - m1) * sl2e);
            sum0 += p0 + p1; sum1 += p2 + p3;
            pack_hilo(p0, p1, Ph0[j], Pl0[j]);
            pack_hilo(p2, p3, Ph1[j], Pl1[j]);
        }
        sum0 += __shfl_xor_sync(0xffffffffu, sum0, 1);
        sum0 += __shfl_xor_sync(0xffffffffu, sum0, 2);
        sum1 += __shfl_xor_sync(0xffffffffu, sum1, 1);
        sum1 += __shfl_xor_sync(0xffffffffu, sum1, 2);
        l0s = l0s * corr0 + sum0;
        l1s = l1s * corr1 + sum1;

        #pragma unroll
        for (int j = 0; j < 16; j++) {
            o[j][0] *= corr0; o[j][1] *= corr0;
            o[j][2] *= corr1; o[j][3] *= corr1;
        }

        if (more) CP_WAIT(1); else CP_WAIT(0);
        __syncthreads();

        #pragma unroll
        for (int kk = 0; kk < 4; kk++) {
            uint32_t ah[4] = {Ph0[2 * kk], Ph1[2 * kk], Ph0[2 * kk + 1], Ph1[2 * kk + 1]};
            uint32_t al[4] = {Pl0[2 * kk], Pl1[2 * kk], Pl0[2 * kk + 1], Pl1[2 * kk + 1]};
            #pragma unroll
            for (int jn = 0; jn < 16; jn++) {
                uint32_t bh[2], bl[2];
                int vb = (jn * 8 + g) * VW + kk * 8 + cc;
                bh[0] = sw[VTH_OFF + vb]; bh[1] = sw[VTH_OFF + vb + 4];
                bl[0] = sw[VTL_OFF + vb]; bl[1] = sw[VTL_OFF + vb + 4];
                mma_bf16(o[jn], ah, bh);
                mma_bf16(o[jn], al, bh);
                mma_bf16(o[jn], ah, bl);
            }
        }
    }

    float li0 = 1.0f / l0s, li1 = 1.0f / l1s;
    #pragma unroll
    for (int jn = 0; jn < 16; jn++) {
        int col = h * HDIM + jn * 8 + 2 * cc;
        *(float2*)&g_o[(size_t)r0 * DMODEL + col] =
            make_float2(f32_to_tf32(o[jn][0] * li0), f32_to_tf32(o[jn][1] * li0));
        *(float2*)&g_o[(size_t)r1 * DMODEL + col] =
            make_float2(f32_to_tf32(o[jn][2] * li1), f32_to_tf32(o[jn][3] * li1));
    }
}

// ---------------------------------------------------------------------------
// Launch
// ---------------------------------------------------------------------------
extern "C" void kernel_launch(void* const* d_in, const int* in_sizes, int n_in,
                              void* d_out, int out_size)
{
    const float* x     = (const float*)d_in[0];
    const float* cosp  = (const float*)d_in[2];
    const float* sinp  = (const float*)d_in[3];
    const float* w_qkv = (const float*)d_in[4];
    const float* w_o   = (const float*)d_in[5];
    float* out = (float*)d_out;

    float *qkv_p, *o_p, *xr_p, *wqkvT_p, *woT_p;
    cudaGetSymbolAddress((void**)&qkv_p, g_qkv);
    cudaGetSymbolAddress((void**)&o_p, g_o);
    cudaGetSymbolAddress((void**)&xr_p, g_xr);
    cudaGetSymbolAddress((void**)&wqkvT_p, g_wqkvT);
    cudaGetSymbolAddress((void**)&woT_p, g_woT);

    cudaFuncSetAttribute(gemm_mma, cudaFuncAttributeMaxDynamicSharedMemorySize, GEMM_SMEM);
    cudaFuncSetAttribute(attn_kernel, cudaFuncAttributeMaxDynamicSharedMemorySize, ATT_SMEM_BYTES);

    // 0. tf32-round inputs / transpose weights to K-major
    rna_copy<<<(LSEQ * DMODEL / 4 + 255) / 256, 256>>>(x, xr_p, LSEQ * DMODEL / 4);
    transpose_rna<<<dim3(QKVN / 32, DMODEL / 32), dim3(32, 8)>>>(w_qkv, wqkvT_p, DMODEL, QKVN);
    transpose_rna<<<dim3(DMODEL / 32, DMODEL / 32), dim3(32, 8)>>>(w_o, woT_p, DMODEL, DMODEL);

    // 1. QKV projection (tf32 mma, mbarrier pipeline)
    gemm_mma<<<dim3(QKVN / BN, LSEQ / BM), 256, GEMM_SMEM>>>(xr_p, wqkvT_p, qkv_p, QKVN, DMODEL);

    // 2. RoPE
    rope_kernel<<<dim3(LSEQ, 10), 256>>>(cosp, sinp);

    // 3. Pack K / V^T to bf16 hi/lo once
    pack_k_kernel<<<dim3(LSEQ / 4, NKV), 256>>>();
    pack_vt_kernel<<<dim3(LSEQ / 64, NKV), 256>>>();

    // 4. Flash attention
    attn_kernel<<<dim3(LSEQ / 128, NH), 256, ATT_SMEM_BYTES>>>();

    // 5. Output projection (tf32 mma, mbarrier pipeline)
    gemm_mma<<<dim3(DMODEL / BN, LSEQ / BM), 256, GEMM_SMEM>>>(o_p, woT_p, out, DMODEL, DMODEL);
}